// round 16
// baseline (speedup 1.0000x reference)
#include <cuda_runtime.h>
#include <math.h>

#define B_  2
#define L_  2048
#define D_  2048
#define H_  16
#define HD_ 128

// Scratch (static __device__ — no runtime allocation)
__device__ float g_q[(size_t)B_ * H_ * L_ * HD_];   // d-permuted within 8, roped
__device__ float g_k[(size_t)B_ * H_ * L_ * HD_];   // d-permuted within 8, roped
__device__ float g_v[(size_t)B_ * H_ * L_ * HD_];   // TRANSPOSED [bh][d][st(l)]
__device__ float g_c[(size_t)B_ * L_ * H_ * HD_];   // col-permuted within 8
__device__ float g_xt[(size_t)B_ * L_ * D_];        // col-permuted within 8
__device__ float g_w0[(size_t)D_ * H_ * HD_];
__device__ float g_w1[(size_t)D_ * H_ * HD_];
__device__ float g_w2[(size_t)D_ * H_ * HD_];
__device__ float g_w3[(size_t)D_ * H_ * HD_];
__device__ float2 g_tab[(size_t)L_ * 64];           // rope (cos,sin) table

__device__ __forceinline__ unsigned f2tf32(float f) {
    unsigned u;
    asm("cvt.rna.tf32.f32 %0, %1;" : "=r"(u) : "f"(f));
    return u;
}
__device__ __forceinline__ float rnd(float f) { return __uint_as_float(f2tf32(f)); }

__device__ __forceinline__ void mma_tf32(float* c, const unsigned* a,
                                         unsigned b0, unsigned b1) {
    asm volatile(
        "mma.sync.aligned.m16n8k8.row.col.f32.tf32.tf32.f32 "
        "{%0,%1,%2,%3},{%4,%5,%6,%7},{%8,%9},{%0,%1,%2,%3};\n"
        : "+f"(c[0]), "+f"(c[1]), "+f"(c[2]), "+f"(c[3])
        : "r"(a[0]), "r"(a[1]), "r"(a[2]), "r"(a[3]), "r"(b0), "r"(b1));
}

__device__ __forceinline__ void cp16(void* smp, const void* g) {
    unsigned s = (unsigned)__cvta_generic_to_shared(smp);
    asm volatile("cp.async.cg.shared.global [%0], [%1], 16;" :: "r"(s), "l"(g));
}

// ---------------------------------------------------------------------------
// Fused tf32 pre-round (R12) + rope table build.
//  x: column-permuted within each 8 (0,4,1,5,2,6,3,7); weights rounded.
//  tab[l][j] = sincos(l * 10000^(-j/64)) — byte-identical to old rope_kernel.
// ---------------------------------------------------------------------------
__global__ void cvt_all_kernel(
    const float4* __restrict__ x,  float4* __restrict__ xt,
    const float4* __restrict__ a0, float4* __restrict__ o0,
    const float4* __restrict__ a1, float4* __restrict__ o1,
    const float4* __restrict__ a2, float4* __restrict__ o2,
    const float4* __restrict__ a3, float4* __restrict__ o3,
    float2* __restrict__ tab)
{
    const int GX = (B_ * L_ * D_) / 8;       // 2^20
    const int NW = (D_ * H_ * HD_) / 4;      // 2^20
    const int NT = L_ * 64;                  // 131072
    int i = blockIdx.x * blockDim.x + threadIdx.x;
    int stride = gridDim.x * blockDim.x;
    for (; i < GX + 4 * NW + NT; i += stride) {
        if (i < GX) {
            float4 lo = x[2 * i], hi = x[2 * i + 1];
            xt[2 * i]     = make_float4(rnd(lo.x), rnd(hi.x), rnd(lo.y), rnd(hi.y));
            xt[2 * i + 1] = make_float4(rnd(lo.z), rnd(hi.z), rnd(lo.w), rnd(hi.w));
        } else if (i < GX + 4 * NW) {
            int j = i - GX; int w = j >> 20; int o = j & (NW - 1);
            const float4* src; float4* dst;
            switch (w) {
                case 0: src = a0; dst = o0; break;
                case 1: src = a1; dst = o1; break;
                case 2: src = a2; dst = o2; break;
                default: src = a3; dst = o3; break;
            }
            float4 v = src[o];
            dst[o] = make_float4(rnd(v.x), rnd(v.y), rnd(v.z), rnd(v.w));
        } else {
            int t = i - GX - 4 * NW;
            int j = t & 63, l = t >> 6;
            float freq = expf(-9.210340371976184f * (float)j * (1.0f / 64.0f));
            float ang = (float)l * freq;
            float s, c;
            sincosf(ang, &s, &c);
            tab[t] = make_float2(c, s);
        }
    }
}

// ---------------------------------------------------------------------------
// GEMM mainloop constants (R12 layout, verified).
// ---------------------------------------------------------------------------
#define AS_LD 40
#define BS_LD 136
#define ST_A (128 * AS_LD)
#define ST_B (32 * BS_LD)
#define ST_W (ST_A + ST_B)
#define GEMM_SMEM (3 * ST_W * 4)    // 113664 B
#define CST_LD 130                  // acc stage pitch (epilogue rope fusion)

// ---------------------------------------------------------------------------
// Merged Q/K/V projection GEMM (R12 mainloop). Epilogue:
//   z=0/1 (q/k): stage acc -> RoPE via precomputed table (zero MUFU) ->
//                d-permuted scatter. Bit-identical to old rope_kernel.
//   z=2   (v):   transposed + key-permuted scatter, tf32-rounded.
// ---------------------------------------------------------------------------
__global__ __launch_bounds__(256, 2) void gemm_qkv(
    const float* __restrict__ A,
    const float* __restrict__ W0, const float* __restrict__ W1,
    const float* __restrict__ W2,
    float* __restrict__ qb, float* __restrict__ kb, float* __restrict__ vb,
    const float2* __restrict__ tab)
{
    extern __shared__ unsigned smu[];

    const int K = D_, N = H_ * HD_;
    const int bz = blockIdx.z;
    const float* Bm = (bz == 0) ? W0 : (bz == 1) ? W1 : W2;
    float* C = (bz == 0) ? qb : (bz == 1) ? kb : vb;

    const int tid  = threadIdx.x;
    const int warp = tid >> 5, lane = tid & 31;
    const int qr = lane >> 2, qc = lane & 3;
    const int wm = (warp & 1) * 64;
    const int wn = (warp >> 1) * 32;
    const int bm = blockIdx.y * 128, bn = blockIdx.x * 128;

    const int rA = tid >> 3, cA = (tid & 7) * 4;
    const int rB = tid >> 5, cB = (tid & 31) * 4;

    const float* Agl = A + (size_t)(bm + rA) * K + cA;
    const float* Bgl = Bm + (size_t)rB * N + bn + cB;

    float acc[4][4][4];
#pragma unroll
    for (int mt = 0; mt < 4; mt++)
#pragma unroll
        for (int nt = 0; nt < 4; nt++)
#pragma unroll
            for (int u = 0; u < 4; u++) acc[mt][nt][u] = 0.f;

    const int NCHUNK = K >> 5;

    auto issue = [&](int s, int k0) {
        unsigned* As = smu + s * ST_W;
        unsigned* Bs = As + ST_A;
#pragma unroll
        for (int it = 0; it < 4; it++)
            cp16(&As[(rA + it * 32) * AS_LD + cA], Agl + (size_t)(it * 32) * K + k0);
#pragma unroll
        for (int it = 0; it < 4; it++)
            cp16(&Bs[(rB + it * 8) * BS_LD + cB], Bgl + (size_t)(k0 + it * 8) * N);
        asm volatile("cp.async.commit_group;");
    };

    issue(0, 0);
    issue(1, 32);

    int cur = 0, pf = 2;
    for (int ch = 0; ch < NCHUNK; ch++) {
        asm volatile("cp.async.wait_group 1;");
        __syncthreads();

        if (ch + 2 < NCHUNK) {
            issue(pf, (ch + 2) << 5);
        } else {
            asm volatile("cp.async.commit_group;");
        }

        const unsigned* As = smu + cur * ST_W;
        const unsigned* Bs = As + ST_A;

#pragma unroll
        for (int s = 0; s < 4; s++) {
            const int kb8 = s * 8;
            unsigned a[4][4], b[4][2];
#pragma unroll
            for (int mt = 0; mt < 4; mt++) {
                int m = wm + mt * 16 + qr;
                uint2 t0 = *(const uint2*)&As[m * AS_LD + kb8 + 2 * qc];
                uint2 t1 = *(const uint2*)&As[(m + 8) * AS_LD + kb8 + 2 * qc];
                a[mt][0] = t0.x; a[mt][2] = t0.y;
                a[mt][1] = t1.x; a[mt][3] = t1.y;
            }
#pragma unroll
            for (int nt = 0; nt < 4; nt++) {
                int n = wn + nt * 8 + qr;
                b[nt][0] = Bs[(kb8 + qc) * BS_LD + n];
                b[nt][1] = Bs[(kb8 + qc + 4) * BS_LD + n];
            }
#pragma unroll
            for (int mt = 0; mt < 4; mt++)
#pragma unroll
                for (int nt = 0; nt < 4; nt++)
                    mma_tf32(acc[mt][nt], a[mt], b[nt][0], b[nt][1]);
        }

        cur = (cur == 2) ? 0 : cur + 1;
        pf  = (pf  == 2) ? 0 : pf  + 1;
    }

    if (bz != 2) {
        // ---- q/k: stage -> table-RoPE -> d-permuted scatter ----
        asm volatile("cp.async.wait_group 0;");
        __syncthreads();
        float* Cst = (float*)smu;
#pragma unroll
        for (int mt = 0; mt < 4; mt++)
#pragma unroll
            for (int nt = 0; nt < 4; nt++) {
                int r = wm + mt * 16 + qr;
                int cl = wn + nt * 8 + 2 * qc;
                Cst[r * CST_LD + cl]           = acc[mt][nt][0];
                Cst[r * CST_LD + cl + 1]       = acc[mt][nt][1];
                Cst[(r + 8) * CST_LD + cl]     = acc[mt][nt][2];
                Cst[(r + 8) * CST_LD + cl + 1] = acc[mt][nt][3];
            }
        __syncthreads();

        const int r  = tid >> 1;              // local row 0..127
        const int j0 = (tid & 1) * 32;        // j range base
        const int row = bm + r;
        const int b0 = row >> 11, l0 = row & (L_ - 1);
        const int h = blockIdx.x;             // block covers one full head
        float* base = C + (((size_t)b0 * H_ + h) * L_ + l0) * HD_;
        const float2* trow = tab + (size_t)l0 * 64 + j0;
#pragma unroll 8
        for (int jj = 0; jj < 32; jj++) {
            int j = j0 + jj;
            float2 cs = trow[jj];
            float q1 = Cst[r * CST_LD + j];
            float q2 = Cst[r * CST_LD + j + 64];
            int c7 = j & 7;
            int jp = (j & ~7) | (2 * (c7 & 3) + (c7 >> 2));
            base[jp]      = rnd(q1 * cs.x - q2 * cs.y);
            base[jp + 64] = rnd(q1 * cs.y + q2 * cs.x);
        }
    } else {
        // ---- V: transposed + key-permuted scatter, tf32-rounded ----
#pragma unroll
        for (int mt = 0; mt < 4; mt++) {
#pragma unroll
            for (int nt = 0; nt < 4; nt++) {
                int row = bm + wm + mt * 16 + qr;
                int col = bn + wn + nt * 8 + 2 * qc;
                int b0 = row >> 11, l0 = row & (L_ - 1);
                int h = col >> 7, d = col & (HD_ - 1);
                int c7 = l0 & 7;
                int stl = (l0 & ~7) | (2 * (c7 & 3) + (c7 >> 2));
                size_t vb2 = (((size_t)(b0 * H_ + h)) * HD_ + d) * L_ + stl;
                C[vb2]          = rnd(acc[mt][nt][0]);
                C[vb2 + L_]     = rnd(acc[mt][nt][1]);
                C[vb2 + 8]      = rnd(acc[mt][nt][2]);
                C[vb2 + L_ + 8] = rnd(acc[mt][nt][3]);
            }
        }
    }
}

// ---------------------------------------------------------------------------
// Output GEMM (R12, verified): natural row-major out.
// ---------------------------------------------------------------------------
__global__ __launch_bounds__(256, 2) void gemm_out(
    const float* __restrict__ A, const float* __restrict__ Bm,
    float* __restrict__ C, int M, int N, int K)
{
    extern __shared__ unsigned smu[];

    const int tid  = threadIdx.x;
    const int warp = tid >> 5, lane = tid & 31;
    const int qr = lane >> 2, qc = lane & 3;
    const int wm = (warp & 1) * 64;
    const int wn = (warp >> 1) * 32;
    const int bm = blockIdx.y * 128, bn = blockIdx.x * 128;

    const int rA = tid >> 3, cA = (tid & 7) * 4;
    const int rB = tid >> 5, cB = (tid & 31) * 4;

    const float* Agl = A + (size_t)(bm + rA) * K + cA;
    const float* Bgl = Bm + (size_t)rB * N + bn + cB;

    float acc[4][4][4];
#pragma unroll
    for (int mt = 0; mt < 4; mt++)
#pragma unroll
        for (int nt = 0; nt < 4; nt++)
#pragma unroll
            for (int u = 0; u < 4; u++) acc[mt][nt][u] = 0.f;

    const int NCHUNK = K >> 5;

    auto issue = [&](int s, int k0) {
        unsigned* As = smu + s * ST_W;
        unsigned* Bs = As + ST_A;
#pragma unroll
        for (int it = 0; it < 4; it++)
            cp16(&As[(rA + it * 32) * AS_LD + cA], Agl + (size_t)(it * 32) * K + k0);
#pragma unroll
        for (int it = 0; it < 4; it++)
            cp16(&Bs[(rB + it * 8) * BS_LD + cB], Bgl + (size_t)(k0 + it * 8) * N);
        asm volatile("cp.async.commit_group;");
    };

    issue(0, 0);
    issue(1, 32);

    int cur = 0, pf = 2;
    for (int ch = 0; ch < NCHUNK; ch++) {
        asm volatile("cp.async.wait_group 1;");
        __syncthreads();

        if (ch + 2 < NCHUNK) {
            issue(pf, (ch + 2) << 5);
        } else {
            asm volatile("cp.async.commit_group;");
        }

        const unsigned* As = smu + cur * ST_W;
        const unsigned* Bs = As + ST_A;

#pragma unroll
        for (int s = 0; s < 4; s++) {
            const int kb8 = s * 8;
            unsigned a[4][4], b[4][2];
#pragma unroll
            for (int mt = 0; mt < 4; mt++) {
                int m = wm + mt * 16 + qr;
                uint2 t0 = *(const uint2*)&As[m * AS_LD + kb8 + 2 * qc];
                uint2 t1 = *(const uint2*)&As[(m + 8) * AS_LD + kb8 + 2 * qc];
                a[mt][0] = t0.x; a[mt][2] = t0.y;
                a[mt][1] = t1.x; a[mt][3] = t1.y;
            }
#pragma unroll
            for (int nt = 0; nt < 4; nt++) {
                int n = wn + nt * 8 + qr;
                b[nt][0] = Bs[(kb8 + qc) * BS_LD + n];
                b[nt][1] = Bs[(kb8 + qc + 4) * BS_LD + n];
            }
#pragma unroll
            for (int mt = 0; mt < 4; mt++)
#pragma unroll
                for (int nt = 0; nt < 4; nt++)
                    mma_tf32(acc[mt][nt], a[mt], b[nt][0], b[nt][1]);
        }

        cur = (cur == 2) ? 0 : cur + 1;
        pf  = (pf  == 2) ? 0 : pf  + 1;
    }

#pragma unroll
    for (int mt = 0; mt < 4; mt++) {
#pragma unroll
        for (int nt = 0; nt < 4; nt++) {
            int row = bm + wm + mt * 16 + qr;
            int col = bn + wn + nt * 8 + 2 * qc;
            float2 r0 = make_float2(acc[mt][nt][0], acc[mt][nt][1]);
            float2 r1 = make_float2(acc[mt][nt][2], acc[mt][nt][3]);
            *(float2*)(C + (size_t)row * N + col) = r0;
            *(float2*)(C + (size_t)(row + 8) * N + col) = r1;
        }
    }
}

// ---------------------------------------------------------------------------
// Attention (R12, verified — unchanged).
// ---------------------------------------------------------------------------
#define K0_OFF 0
#define K1_OFF 8704
#define V0_OFF 17408
#define V1_OFF 26624
#define PS_OFF 35840
#define MS_OFF 0
#define NS_OFF 35840
#define LDK 136
#define LDVT 72
#define LDP 68
#define LDM 136
#define ATTN_SMEM (44544 * 4)   // 178176 B

__global__ __launch_bounds__(256, 1) void attn_tc(
    const float* __restrict__ qb, const float* __restrict__ kb,
    const float* __restrict__ vb, const float* __restrict__ gatep,
    const float* __restrict__ memp, const float* __restrict__ normp,
    float* __restrict__ cb)
{
    extern __shared__ float smf[];
    unsigned* smu = (unsigned*)smf;

    const int tid = threadIdx.x;
    const int w = tid >> 5, lane = tid & 31;
    const int qr = lane >> 2, qc = lane & 3;
    const int qt = blockIdx.x;
    const int bh = blockIdx.y;
    const int h  = bh & (H_ - 1);
    const int b  = bh >> 4;
    const int m0 = w * 16 + qr;

    const float* qblk  = qb + ((size_t)bh * L_ + qt * 128) * HD_;
    const float* kbase = kb + (size_t)bh * L_ * HD_;
    const float* vbase = vb + (size_t)bh * HD_ * L_;

    auto issue_kv = [&](int kt) {
        unsigned kOff = (kt & 1) ? K1_OFF : K0_OFF;
        unsigned vOff = (kt & 1) ? V1_OFF : V0_OFF;
#pragma unroll
        for (int it = 0; it < 8; it++) {
            int item = tid + it * 256;
            int row = item >> 5, colf = (item & 31) * 4;
            cp16(&smu[kOff + row * LDK + colf],
                 kbase + (size_t)(kt * 64 + row) * HD_ + colf);
        }
#pragma unroll
        for (int it = 0; it < 8; it++) {
            int item = tid + it * 256;
            int d = item >> 4, ch = (item & 15) * 4;
            cp16(&smu[vOff + d * LDVT + ch],
                 vbase + (size_t)d * L_ + kt * 64 + ch);
        }
        asm volatile("cp.async.commit_group;");
    };

    issue_kv(0);

    unsigned qa[16][4];
#pragma unroll
    for (int ks = 0; ks < 16; ks++) {
        uint2 t0 = *(const uint2*)&qblk[(size_t)m0 * HD_ + 8 * ks + 2 * qc];
        uint2 t1 = *(const uint2*)&qblk[(size_t)(m0 + 8) * HD_ + 8 * ks + 2 * qc];
        qa[ks][0] = t0.x; qa[ks][2] = t0.y;
        qa[ks][1] = t1.x; qa[ks][3] = t1.y;
    }

    float o[16][4];
#pragma unroll
    for (int nt = 0; nt < 16; nt++)
#pragma unroll
        for (int u = 0; u < 4; u++) o[nt][u] = 0.f;
    float mrow0 = -1e30f, mrow1 = -1e30f;
    float lrow0 = 0.f, lrow1 = 0.f;

    const float scale = 0.08838834764831845f;

    for (int kt = 0; kt < 32; kt++) {
        asm volatile("cp.async.wait_group 0;");
        __syncthreads();
        if (kt + 1 < 32) issue_kv(kt + 1);

        const unsigned* Kb = smu + ((kt & 1) ? K1_OFF : K0_OFF);
        const unsigned* Vb = smu + ((kt & 1) ? V1_OFF : V0_OFF);

        float sa[8][4];
#pragma unroll
        for (int nt = 0; nt < 8; nt++)
#pragma unroll
            for (int u = 0; u < 4; u++) sa[nt][u] = 0.f;

#pragma unroll
        for (int ks = 0; ks < 16; ks++) {
            const int kb8 = ks * 8;
#pragma unroll
            for (int nt = 0; nt < 8; nt++) {
                int n = nt * 8 + qr;
                uint2 bb = *(const uint2*)&Kb[n * LDK + kb8 + 2 * qc];
                mma_tf32(sa[nt], qa[ks], bb.x, bb.y);
            }
        }

        float cand0 = -1e30f, cand1 = -1e30f;
#pragma unroll
        for (int nt = 0; nt < 8; nt++) {
            cand0 = fmaxf(cand0, fmaxf(sa[nt][0], sa[nt][1]));
            cand1 = fmaxf(cand1, fmaxf(sa[nt][2], sa[nt][3]));
        }
        cand0 *= scale; cand1 *= scale;
        cand0 = fmaxf(cand0, __shfl_xor_sync(0xffffffffu, cand0, 1));
        cand0 = fmaxf(cand0, __shfl_xor_sync(0xffffffffu, cand0, 2));
        cand1 = fmaxf(cand1, __shfl_xor_sync(0xffffffffu, cand1, 1));
        cand1 = fmaxf(cand1, __shfl_xor_sync(0xffffffffu, cand1, 2));

        float newm0 = fmaxf(mrow0, cand0), newm1 = fmaxf(mrow1, cand1);
        float corr0 = __expf(mrow0 - newm0), corr1 = __expf(mrow1 - newm1);
        mrow0 = newm0; mrow1 = newm1;

        float psum0 = 0.f, psum1 = 0.f;
#pragma unroll
        for (int nt = 0; nt < 8; nt++) {
            float p0 = __expf(sa[nt][0] * scale - newm0);
            float p1 = __expf(sa[nt][1] * scale - newm0);
            float p2 = __expf(sa[nt][2] * scale - newm1);
            float p3 = __expf(sa[nt][3] * scale - newm1);
            psum0 += p0 + p1; psum1 += p2 + p3;
            float2 lo, hi;
            lo.x = rnd(p0); lo.y = rnd(p1);
            hi.x = rnd(p2); hi.y = rnd(p3);
            *(float2*)&smf[PS_OFF + m0 * LDP + nt * 8 + 2 * qc] = lo;
            *(float2*)&smf[PS_OFF + (m0 + 8) * LDP + nt * 8 + 2 * qc] = hi;
        }
        psum0 += __shfl_xor_sync(0xffffffffu, psum0, 1);
        psum0 += __shfl_xor_sync(0xffffffffu, psum0, 2);
        psum1 += __shfl_xor_sync(0xffffffffu, psum1, 1);
        psum1 += __shfl_xor_sync(0xffffffffu, psum1, 2);
        lrow0 = lrow0 * corr0 + psum0;
        lrow1 = lrow1 * corr1 + psum1;

#pragma unroll
        for (int nt = 0; nt < 16; nt++) {
            o[nt][0] *= corr0; o[nt][1] *= corr0;
            o[nt][2] *= corr1; o[nt][3] *= corr1;
        }
        __syncwarp();

#pragma unroll
        for (int ks = 0; ks < 8; ks++) {
            const int kb8 = ks * 8;
            unsigned a[4];
            a[0] = __float_as_uint(smf[PS_OFF + m0 * LDP + kb8 + qc]);
            a[1] = __float_as_uint(smf[PS_OFF + (m0 + 8) * LDP + kb8 + qc]);
            a[2] = __float_as_uint(smf[PS_OFF + m0 * LDP + kb8 + qc + 4]);
            a[3] = __float_as_uint(smf[PS_OFF + (m0 + 8) * LDP + kb8 + qc + 4]);
#pragma unroll
            for (int nt = 0; nt < 16; nt++) {
                int n = nt * 8 + qr;
                uint2 bb = *(const uint2*)&Vb[n * LDVT + kb8 + 2 * qc];
                mma_tf32(o[nt], a, bb.x, bb.y);
            }
        }
    }

    // ================== epilogue: memory path ==================
    __syncthreads();

    const float* mptr = memp + (size_t)bh * HD_ * HD_;
#pragma unroll
    for (int it = 0; it < 16; it++) {
        int row = w + 8 * it;
        float4 v = *(const float4*)(mptr + (size_t)row * HD_ + lane * 4);
        *(uint4*)&smu[MS_OFF + row * LDM + lane * 4] =
            make_uint4(f2tf32(v.x), f2tf32(v.y), f2tf32(v.z), f2tf32(v.w));
    }
    if (tid < 128) smf[NS_OFF + tid] = normp[(size_t)bh * HD_ + tid];

#pragma unroll
    for (int ks = 0; ks < 16; ks++)
#pragma unroll
        for (int u = 0; u < 4; u++) {
            float qv = __uint_as_float(qa[ks][u]);
            float qf = qv > 0.f ? qv + 1.f : __expf(qv);
            qa[ks][u] = f2tf32(qf);
        }
    __syncthreads();

    float den0 = 0.f, den1 = 0.f;
#pragma unroll
    for (int ks = 0; ks < 16; ks++) {
        float n0 = smf[NS_OFF + 8 * ks + qc];
        float n4 = smf[NS_OFF + 8 * ks + qc + 4];
        den0 = fmaf(__uint_as_float(qa[ks][0]), n0, den0);
        den0 = fmaf(__uint_as_float(qa[ks][2]), n4, den0);
        den1 = fmaf(__uint_as_float(qa[ks][1]), n0, den1);
        den1 = fmaf(__uint_as_float(qa[ks][3]), n4, den1);
    }
    den0 += __shfl_xor_sync(0xffffffffu, den0, 1);
    den0 += __shfl_xor_sync(0xffffffffu, den0, 2);
    den1 += __shfl_xor_sync(0xffffffffu, den1, 1);
    den1 += __shfl_xor_sync(0xffffffffu, den1, 2);

    const float g  = 1.f / (1.f + __expf(-gatep[h]));
    const float og = 1.f - g;
    const float invl0 = og / lrow0, invl1 = og / lrow1;
    const float invd0 = g / den0,   invd1 = g / den1;

    const int l0 = qt * 128 + m0;
    float* dst0 = cb + ((size_t)b * L_ + l0) * (H_ * HD_) + h * HD_;
    float* dst1 = cb + ((size_t)b * L_ + l0 + 8) * (H_ * HD_) + h * HD_;

    const int p8 = (qc < 2) ? 4 * qc : 4 * (qc - 2) + 1;

#pragma unroll
    for (int pass = 0; pass < 2; pass++) {
        float ma[8][4];
#pragma unroll
        for (int nt = 0; nt < 8; nt++)
#pragma unroll
            for (int u = 0; u < 4; u++) ma[nt][u] = 0.f;

#pragma unroll
        for (int ks = 0; ks < 16; ks++) {
            const int kb8 = ks * 8;
#pragma unroll
            for (int nt = 0; nt < 8; nt++) {
                int n = (pass * 8 + nt) * 8 + qr;
                unsigned b0 = smu[MS_OFF + (kb8 + qc) * LDM + n];
                unsigned b1 = smu[MS_OFF + (kb8 + qc + 4) * LDM + n];
                mma_tf32(ma[nt], qa[ks], b0, b1);
            }
        }

#pragma unroll
        for (int nt = 0; nt < 8; nt++) {
            int gnt = pass * 8 + nt;
            int grp = gnt * 8;
            float r00 = rnd(ma[nt][0] * invd0 + o[gnt][0] * invl0);
            float r01 = rnd(ma[nt][1] * invd0 + o[gnt][1] * invl0);
            float r10 = rnd(ma[nt][2] * invd1 + o[gnt][2] * invl1);
            float r11 = rnd(ma[nt][3] * invd1 + o[gnt][3] * invl1);
            dst0[grp + p8]     = r00;
            dst0[grp + p8 + 2] = r01;
            dst1[grp + p8]     = r10;
            dst1[grp + p8 + 2] = r11;
        }
    }
}

// ---------------------------------------------------------------------------

extern "C" void kernel_launch(void* const* d_in, const int* in_sizes, int n_in,
                              void* d_out, int out_size)
{
    const float* x      = (const float*)d_in[0];
    const float* Wq     = (const float*)d_in[1];
    const float* Wk     = (const float*)d_in[2];
    const float* Wv     = (const float*)d_in[3];
    const float* Wo     = (const float*)d_in[4];
    const float* gate   = (const float*)d_in[5];
    const float* memory = (const float*)d_in[6];
    const float* norm   = (const float*)d_in[7];
    float* out = (float*)d_out;

    float *qb, *kb, *vb, *cb, *xt, *w0, *w1, *w2, *w3;
    float2* tb;
    cudaGetSymbolAddress((void**)&qb, g_q);
    cudaGetSymbolAddress((void**)&kb, g_k);
    cudaGetSymbolAddress((void**)&vb, g_v);
    cudaGetSymbolAddress((void**)&cb, g_c);
    cudaGetSymbolAddress((void**)&xt, g_xt);
    cudaGetSymbolAddress((void**)&w0, g_w0);
    cudaGetSymbolAddress((void**)&w1, g_w1);
    cudaGetSymbolAddress((void**)&w2, g_w2);
    cudaGetSymbolAddress((void**)&w3, g_w3);
    cudaGetSymbolAddress((void**)&tb, g_tab);

    // launch 0: fused tf32 pre-rounding + rope table
    cvt_all_kernel<<<2048, 256>>>(
        (const float4*)x,  (float4*)xt,
        (const float4*)Wq, (float4*)w0,
        (const float4*)Wk, (float4*)w1,
        (const float4*)Wv, (float4*)w2,
        (const float4*)Wo, (float4*)w3, tb);

    cudaFuncSetAttribute(gemm_qkv, cudaFuncAttributeMaxDynamicSharedMemorySize, GEMM_SMEM);
    cudaFuncSetAttribute(gemm_out, cudaFuncAttributeMaxDynamicSharedMemorySize, GEMM_SMEM);

    // launch 1: merged Q/K/V projections with table-RoPE fused epilogue
    gemm_qkv<<<dim3(16, 32, 3), 256, GEMM_SMEM>>>(xt, w0, w1, w2, qb, kb, vb, tb);

    // launch 2: attention
    cudaFuncSetAttribute(attn_tc, cudaFuncAttributeMaxDynamicSharedMemorySize, ATTN_SMEM);
    attn_tc<<<dim3(16, 32), 256, ATTN_SMEM>>>(qb, kb, vb, gate, memory, norm, cb);

    // launch 3: output projection (ncu capture slot)
    gemm_out<<<dim3(16, 32), 256, GEMM_SMEM>>>(cb, w3, out, B_ * L_, H_ * HD_, D_);
}

// round 17
// speedup vs baseline: 1.0585x; 1.0585x over previous
#include <cuda_runtime.h>
#include <math.h>

#define B_  2
#define L_  2048
#define D_  2048
#define H_  16
#define HD_ 128

// Scratch (static __device__ — no runtime allocation)
__device__ float g_q[(size_t)B_ * H_ * L_ * HD_];   // d-permuted within 8
__device__ float g_k[(size_t)B_ * H_ * L_ * HD_];   // d-permuted within 8
__device__ float g_v[(size_t)B_ * H_ * L_ * HD_];   // TRANSPOSED [bh][d][st(l)]
__device__ float g_c[(size_t)B_ * L_ * H_ * HD_];   // col-permuted within 8
__device__ float g_xt[(size_t)B_ * L_ * D_];        // col-permuted within 8
__device__ float g_w0[(size_t)D_ * H_ * HD_];
__device__ float g_w1[(size_t)D_ * H_ * HD_];
__device__ float g_w2[(size_t)D_ * H_ * HD_];
__device__ float g_w3[(size_t)D_ * H_ * HD_];

__device__ __forceinline__ unsigned f2tf32(float f) {
    unsigned u;
    asm("cvt.rna.tf32.f32 %0, %1;" : "=r"(u) : "f"(f));
    return u;
}
__device__ __forceinline__ float rnd(float f) { return __uint_as_float(f2tf32(f)); }

__device__ __forceinline__ void mma_tf32(float* c, const unsigned* a,
                                         unsigned b0, unsigned b1) {
    asm volatile(
        "mma.sync.aligned.m16n8k8.row.col.f32.tf32.tf32.f32 "
        "{%0,%1,%2,%3},{%4,%5,%6,%7},{%8,%9},{%0,%1,%2,%3};\n"
        : "+f"(c[0]), "+f"(c[1]), "+f"(c[2]), "+f"(c[3])
        : "r"(a[0]), "r"(a[1]), "r"(a[2]), "r"(a[3]), "r"(b0), "r"(b1));
}

__device__ __forceinline__ void cp16(void* smp, const void* g) {
    unsigned s = (unsigned)__cvta_generic_to_shared(smp);
    asm volatile("cp.async.cg.shared.global [%0], [%1], 16;" :: "r"(s), "l"(g));
}

// ---------------------------------------------------------------------------
// cvt split (R12 math, 3 launches): x column-permuted within each 8
// (0,4,1,5,2,6,3,7); weights rounded in natural layout.
// ---------------------------------------------------------------------------
__global__ void cvt_x_kernel(const float4* __restrict__ x, float4* __restrict__ xt)
{
    const int GX = (B_ * L_ * D_) / 8;       // 2^20 groups
    int i = blockIdx.x * blockDim.x + threadIdx.x;
    int stride = gridDim.x * blockDim.x;
    for (; i < GX; i += stride) {
        float4 lo = x[2 * i], hi = x[2 * i + 1];
        xt[2 * i]     = make_float4(rnd(lo.x), rnd(hi.x), rnd(lo.y), rnd(hi.y));
        xt[2 * i + 1] = make_float4(rnd(lo.z), rnd(hi.z), rnd(lo.w), rnd(hi.w));
    }
}

__global__ void cvt_w_kernel(
    const float4* __restrict__ a0, float4* __restrict__ o0,
    const float4* __restrict__ a1, float4* __restrict__ o1)
{
    const int NW = (D_ * H_ * HD_) / 4;      // 2^20
    int i = blockIdx.x * blockDim.x + threadIdx.x;
    int stride = gridDim.x * blockDim.x;
    for (; i < 2 * NW; i += stride) {
        const float4* src = (i < NW) ? a0 : a1;
        float4* dst = (i < NW) ? o0 : o1;
        int o = i & (NW - 1);
        float4 v = src[o];
        dst[o] = make_float4(rnd(v.x), rnd(v.y), rnd(v.z), rnd(v.w));
    }
}

// ---------------------------------------------------------------------------
// GEMM mainloop constants (R12 layout, verified at 1284us).
// ---------------------------------------------------------------------------
#define AS_LD 40
#define BS_LD 136
#define ST_A (128 * AS_LD)
#define ST_B (32 * BS_LD)
#define ST_W (ST_A + ST_B)
#define GEMM_SMEM (3 * ST_W * 4)    // 113664 B

// ---------------------------------------------------------------------------
// Merged Q/K/V projection GEMM (R12, verified): blockIdx.z selects
// (weight, destination, epilogue mode).
// ---------------------------------------------------------------------------
__global__ __launch_bounds__(256, 2) void gemm_qkv(
    const float* __restrict__ A,
    const float* __restrict__ W0, const float* __restrict__ W1,
    const float* __restrict__ W2,
    float* __restrict__ qb, float* __restrict__ kb, float* __restrict__ vb)
{
    extern __shared__ unsigned smu[];

    const int K = D_, N = H_ * HD_;
    const int bz = blockIdx.z;
    const float* Bm = (bz == 0) ? W0 : (bz == 1) ? W1 : W2;
    float* C = (bz == 0) ? qb : (bz == 1) ? kb : vb;

    const int tid  = threadIdx.x;
    const int warp = tid >> 5, lane = tid & 31;
    const int qr = lane >> 2, qc = lane & 3;
    const int wm = (warp & 1) * 64;
    const int wn = (warp >> 1) * 32;
    const int bm = blockIdx.y * 128, bn = blockIdx.x * 128;

    const int rA = tid >> 3, cA = (tid & 7) * 4;
    const int rB = tid >> 5, cB = (tid & 31) * 4;

    const float* Agl = A + (size_t)(bm + rA) * K + cA;
    const float* Bgl = Bm + (size_t)rB * N + bn + cB;

    float acc[4][4][4];
#pragma unroll
    for (int mt = 0; mt < 4; mt++)
#pragma unroll
        for (int nt = 0; nt < 4; nt++)
#pragma unroll
            for (int u = 0; u < 4; u++) acc[mt][nt][u] = 0.f;

    const int NCHUNK = K >> 5;

    auto issue = [&](int s, int k0) {
        unsigned* As = smu + s * ST_W;
        unsigned* Bs = As + ST_A;
#pragma unroll
        for (int it = 0; it < 4; it++)
            cp16(&As[(rA + it * 32) * AS_LD + cA], Agl + (size_t)(it * 32) * K + k0);
#pragma unroll
        for (int it = 0; it < 4; it++)
            cp16(&Bs[(rB + it * 8) * BS_LD + cB], Bgl + (size_t)(k0 + it * 8) * N);
        asm volatile("cp.async.commit_group;");
    };

    issue(0, 0);
    issue(1, 32);

    int cur = 0, pf = 2;
    for (int ch = 0; ch < NCHUNK; ch++) {
        asm volatile("cp.async.wait_group 1;");
        __syncthreads();

        if (ch + 2 < NCHUNK) {
            issue(pf, (ch + 2) << 5);
        } else {
            asm volatile("cp.async.commit_group;");
        }

        const unsigned* As = smu + cur * ST_W;
        const unsigned* Bs = As + ST_A;

#pragma unroll
        for (int s = 0; s < 4; s++) {
            const int kb8 = s * 8;
            unsigned a[4][4], b[4][2];
#pragma unroll
            for (int mt = 0; mt < 4; mt++) {
                int m = wm + mt * 16 + qr;
                uint2 t0 = *(const uint2*)&As[m * AS_LD + kb8 + 2 * qc];
                uint2 t1 = *(const uint2*)&As[(m + 8) * AS_LD + kb8 + 2 * qc];
                a[mt][0] = t0.x; a[mt][2] = t0.y;
                a[mt][1] = t1.x; a[mt][3] = t1.y;
            }
#pragma unroll
            for (int nt = 0; nt < 4; nt++) {
                int n = wn + nt * 8 + qr;
                b[nt][0] = Bs[(kb8 + qc) * BS_LD + n];
                b[nt][1] = Bs[(kb8 + qc + 4) * BS_LD + n];
            }
#pragma unroll
            for (int mt = 0; mt < 4; mt++)
#pragma unroll
                for (int nt = 0; nt < 4; nt++)
                    mma_tf32(acc[mt][nt], a[mt], b[nt][0], b[nt][1]);
        }

        cur = (cur == 2) ? 0 : cur + 1;
        pf  = (pf  == 2) ? 0 : pf  + 1;
    }

    const int p8 = (qc < 2) ? 4 * qc : 4 * (qc - 2) + 1;

#pragma unroll
    for (int mt = 0; mt < 4; mt++) {
#pragma unroll
        for (int nt = 0; nt < 4; nt++) {
            int row = bm + wm + mt * 16 + qr;
            int col = bn + wn + nt * 8 + 2 * qc;
            if (bz != 2) {
                // q/k: d-permuted scatter
                int b0 = row >> 11, l0 = row & (L_ - 1);
                int h = col >> 7, d = col & (HD_ - 1);
                int dp = (d - 2 * qc) + p8;
                float* base0 = C + ((((size_t)b0 * H_ + h) * L_ + l0) * HD_);
                base0[dp]     = acc[mt][nt][0];
                base0[dp + 2] = acc[mt][nt][1];
                int l1 = l0 + 8;
                float* base1 = C + ((((size_t)b0 * H_ + h) * L_ + l1) * HD_);
                base1[dp]     = acc[mt][nt][2];
                base1[dp + 2] = acc[mt][nt][3];
            } else {
                // V transposed: Vt[bh][d][st(l)], tf32-rounded
                int b0 = row >> 11, l0 = row & (L_ - 1);
                int h = col >> 7, d = col & (HD_ - 1);
                int c7 = l0 & 7;
                int stl = (l0 & ~7) | (2 * (c7 & 3) + (c7 >> 2));
                size_t vb2 = (((size_t)(b0 * H_ + h)) * HD_ + d) * L_ + stl;
                C[vb2]          = rnd(acc[mt][nt][0]);
                C[vb2 + L_]     = rnd(acc[mt][nt][1]);
                C[vb2 + 8]      = rnd(acc[mt][nt][2]);
                C[vb2 + L_ + 8] = rnd(acc[mt][nt][3]);
            }
        }
    }
}

// ---------------------------------------------------------------------------
// Output GEMM (R12, verified): natural row-major out.
// ---------------------------------------------------------------------------
__global__ __launch_bounds__(256, 2) void gemm_out(
    const float* __restrict__ A, const float* __restrict__ Bm,
    float* __restrict__ C, int M, int N, int K)
{
    extern __shared__ unsigned smu[];

    const int tid  = threadIdx.x;
    const int warp = tid >> 5, lane = tid & 31;
    const int qr = lane >> 2, qc = lane & 3;
    const int wm = (warp & 1) * 64;
    const int wn = (warp >> 1) * 32;
    const int bm = blockIdx.y * 128, bn = blockIdx.x * 128;

    const int rA = tid >> 3, cA = (tid & 7) * 4;
    const int rB = tid >> 5, cB = (tid & 31) * 4;

    const float* Agl = A + (size_t)(bm + rA) * K + cA;
    const float* Bgl = Bm + (size_t)rB * N + bn + cB;

    float acc[4][4][4];
#pragma unroll
    for (int mt = 0; mt < 4; mt++)
#pragma unroll
        for (int nt = 0; nt < 4; nt++)
#pragma unroll
            for (int u = 0; u < 4; u++) acc[mt][nt][u] = 0.f;

    const int NCHUNK = K >> 5;

    auto issue = [&](int s, int k0) {
        unsigned* As = smu + s * ST_W;
        unsigned* Bs = As + ST_A;
#pragma unroll
        for (int it = 0; it < 4; it++)
            cp16(&As[(rA + it * 32) * AS_LD + cA], Agl + (size_t)(it * 32) * K + k0);
#pragma unroll
        for (int it = 0; it < 4; it++)
            cp16(&Bs[(rB + it * 8) * BS_LD + cB], Bgl + (size_t)(k0 + it * 8) * N);
        asm volatile("cp.async.commit_group;");
    };

    issue(0, 0);
    issue(1, 32);

    int cur = 0, pf = 2;
    for (int ch = 0; ch < NCHUNK; ch++) {
        asm volatile("cp.async.wait_group 1;");
        __syncthreads();

        if (ch + 2 < NCHUNK) {
            issue(pf, (ch + 2) << 5);
        } else {
            asm volatile("cp.async.commit_group;");
        }

        const unsigned* As = smu + cur * ST_W;
        const unsigned* Bs = As + ST_A;

#pragma unroll
        for (int s = 0; s < 4; s++) {
            const int kb8 = s * 8;
            unsigned a[4][4], b[4][2];
#pragma unroll
            for (int mt = 0; mt < 4; mt++) {
                int m = wm + mt * 16 + qr;
                uint2 t0 = *(const uint2*)&As[m * AS_LD + kb8 + 2 * qc];
                uint2 t1 = *(const uint2*)&As[(m + 8) * AS_LD + kb8 + 2 * qc];
                a[mt][0] = t0.x; a[mt][2] = t0.y;
                a[mt][1] = t1.x; a[mt][3] = t1.y;
            }
#pragma unroll
            for (int nt = 0; nt < 4; nt++) {
                int n = wn + nt * 8 + qr;
                b[nt][0] = Bs[(kb8 + qc) * BS_LD + n];
                b[nt][1] = Bs[(kb8 + qc + 4) * BS_LD + n];
            }
#pragma unroll
            for (int mt = 0; mt < 4; mt++)
#pragma unroll
                for (int nt = 0; nt < 4; nt++)
                    mma_tf32(acc[mt][nt], a[mt], b[nt][0], b[nt][1]);
        }

        cur = (cur == 2) ? 0 : cur + 1;
        pf  = (pf  == 2) ? 0 : pf  + 1;
    }

#pragma unroll
    for (int mt = 0; mt < 4; mt++) {
#pragma unroll
        for (int nt = 0; nt < 4; nt++) {
            int row = bm + wm + mt * 16 + qr;
            int col = bn + wn + nt * 8 + 2 * qc;
            float2 r0 = make_float2(acc[mt][nt][0], acc[mt][nt][1]);
            float2 r1 = make_float2(acc[mt][nt][2], acc[mt][nt][3]);
            *(float2*)(C + (size_t)row * N + col) = r0;
            *(float2*)(C + (size_t)(row + 8) * N + col) = r1;
        }
    }
}

// ---------------------------------------------------------------------------
// RoPE in-place on d-permuted q/k (R12, verified).
// ---------------------------------------------------------------------------
__global__ void rope_kernel(float* __restrict__ qb, float* __restrict__ kb)
{
    int idx = blockIdx.x * blockDim.x + threadIdx.x;
    if (idx >= B_ * H_ * L_ * 64) return;
    int j  = idx & 63;
    int l  = (idx >> 6) & (L_ - 1);
    int bh = idx >> 17;

    float freq = expf(-9.210340371976184f * (float)j * (1.0f / 64.0f));
    float ang = (float)l * freq;
    float s, c;
    sincosf(ang, &s, &c);

    int c7 = j & 7;
    int jp = (j & ~7) | (2 * (c7 & 3) + (c7 >> 2));

    size_t base = ((size_t)bh * L_ + l) * HD_ + jp;
    float q1 = qb[base], q2 = qb[base + 64];
    qb[base]      = rnd(q1 * c - q2 * s);
    qb[base + 64] = rnd(q1 * s + q2 * c);
    float k1 = kb[base], k2 = kb[base + 64];
    kb[base]      = rnd(k1 * c - k2 * s);
    kb[base + 64] = rnd(k1 * s + k2 * c);
}

// ---------------------------------------------------------------------------
// Attention (R12, verified — unchanged).
// ---------------------------------------------------------------------------
#define K0_OFF 0
#define K1_OFF 8704
#define V0_OFF 17408
#define V1_OFF 26624
#define PS_OFF 35840
#define MS_OFF 0
#define NS_OFF 35840
#define LDK 136
#define LDVT 72
#define LDP 68
#define LDM 136
#define ATTN_SMEM (44544 * 4)   // 178176 B

__global__ __launch_bounds__(256, 1) void attn_tc(
    const float* __restrict__ qb, const float* __restrict__ kb,
    const float* __restrict__ vb, const float* __restrict__ gatep,
    const float* __restrict__ memp, const float* __restrict__ normp,
    float* __restrict__ cb)
{
    extern __shared__ float smf[];
    unsigned* smu = (unsigned*)smf;

    const int tid = threadIdx.x;
    const int w = tid >> 5, lane = tid & 31;
    const int qr = lane >> 2, qc = lane & 3;
    const int qt = blockIdx.x;
    const int bh = blockIdx.y;
    const int h  = bh & (H_ - 1);
    const int b  = bh >> 4;
    const int m0 = w * 16 + qr;

    const float* qblk  = qb + ((size_t)bh * L_ + qt * 128) * HD_;
    const float* kbase = kb + (size_t)bh * L_ * HD_;
    const float* vbase = vb + (size_t)bh * HD_ * L_;

    auto issue_kv = [&](int kt) {
        unsigned kOff = (kt & 1) ? K1_OFF : K0_OFF;
        unsigned vOff = (kt & 1) ? V1_OFF : V0_OFF;
#pragma unroll
        for (int it = 0; it < 8; it++) {
            int item = tid + it * 256;
            int row = item >> 5, colf = (item & 31) * 4;
            cp16(&smu[kOff + row * LDK + colf],
                 kbase + (size_t)(kt * 64 + row) * HD_ + colf);
        }
#pragma unroll
        for (int it = 0; it < 8; it++) {
            int item = tid + it * 256;
            int d = item >> 4, ch = (item & 15) * 4;
            cp16(&smu[vOff + d * LDVT + ch],
                 vbase + (size_t)d * L_ + kt * 64 + ch);
        }
        asm volatile("cp.async.commit_group;");
    };

    issue_kv(0);

    unsigned qa[16][4];
#pragma unroll
    for (int ks = 0; ks < 16; ks++) {
        uint2 t0 = *(const uint2*)&qblk[(size_t)m0 * HD_ + 8 * ks + 2 * qc];
        uint2 t1 = *(const uint2*)&qblk[(size_t)(m0 + 8) * HD_ + 8 * ks + 2 * qc];
        qa[ks][0] = t0.x; qa[ks][2] = t0.y;
        qa[ks][1] = t1.x; qa[ks][3] = t1.y;
    }

    float o[16][4];
#pragma unroll
    for (int nt = 0; nt < 16; nt++)
#pragma unroll
        for (int u = 0; u < 4; u++) o[nt][u] = 0.f;
    float mrow0 = -1e30f, mrow1 = -1e30f;
    float lrow0 = 0.f, lrow1 = 0.f;

    const float scale = 0.08838834764831845f;

    for (int kt = 0; kt < 32; kt++) {
        asm volatile("cp.async.wait_group 0;");
        __syncthreads();
        if (kt + 1 < 32) issue_kv(kt + 1);

        const unsigned* Kb = smu + ((kt & 1) ? K1_OFF : K0_OFF);
        const unsigned* Vb = smu + ((kt & 1) ? V1_OFF : V0_OFF);

        float sa[8][4];
#pragma unroll
        for (int nt = 0; nt < 8; nt++)
#pragma unroll
            for (int u = 0; u < 4; u++) sa[nt][u] = 0.f;

#pragma unroll
        for (int ks = 0; ks < 16; ks++) {
            const int kb8 = ks * 8;
#pragma unroll
            for (int nt = 0; nt < 8; nt++) {
                int n = nt * 8 + qr;
                uint2 bb = *(const uint2*)&Kb[n * LDK + kb8 + 2 * qc];
                mma_tf32(sa[nt], qa[ks], bb.x, bb.y);
            }
        }

        float cand0 = -1e30f, cand1 = -1e30f;
#pragma unroll
        for (int nt = 0; nt < 8; nt++) {
            cand0 = fmaxf(cand0, fmaxf(sa[nt][0], sa[nt][1]));
            cand1 = fmaxf(cand1, fmaxf(sa[nt][2], sa[nt][3]));
        }
        cand0 *= scale; cand1 *= scale;
        cand0 = fmaxf(cand0, __shfl_xor_sync(0xffffffffu, cand0, 1));
        cand0 = fmaxf(cand0, __shfl_xor_sync(0xffffffffu, cand0, 2));
        cand1 = fmaxf(cand1, __shfl_xor_sync(0xffffffffu, cand1, 1));
        cand1 = fmaxf(cand1, __shfl_xor_sync(0xffffffffu, cand1, 2));

        float newm0 = fmaxf(mrow0, cand0), newm1 = fmaxf(mrow1, cand1);
        float corr0 = __expf(mrow0 - newm0), corr1 = __expf(mrow1 - newm1);
        mrow0 = newm0; mrow1 = newm1;

        float psum0 = 0.f, psum1 = 0.f;
#pragma unroll
        for (int nt = 0; nt < 8; nt++) {
            float p0 = __expf(sa[nt][0] * scale - newm0);
            float p1 = __expf(sa[nt][1] * scale - newm0);
            float p2 = __expf(sa[nt][2] * scale - newm1);
            float p3 = __expf(sa[nt][3] * scale - newm1);
            psum0 += p0 + p1; psum1 += p2 + p3;
            float2 lo, hi;
            lo.x = rnd(p0); lo.y = rnd(p1);
            hi.x = rnd(p2); hi.y = rnd(p3);
            *(float2*)&smf[PS_OFF + m0 * LDP + nt * 8 + 2 * qc] = lo;
            *(float2*)&smf[PS_OFF + (m0 + 8) * LDP + nt * 8 + 2 * qc] = hi;
        }
        psum0 += __shfl_xor_sync(0xffffffffu, psum0, 1);
        psum0 += __shfl_xor_sync(0xffffffffu, psum0, 2);
        psum1 += __shfl_xor_sync(0xffffffffu, psum1, 1);
        psum1 += __shfl_xor_sync(0xffffffffu, psum1, 2);
        lrow0 = lrow0 * corr0 + psum0;
        lrow1 = lrow1 * corr1 + psum1;

#pragma unroll
        for (int nt = 0; nt < 16; nt++) {
            o[nt][0] *= corr0; o[nt][1] *= corr0;
            o[nt][2] *= corr1; o[nt][3] *= corr1;
        }
        __syncwarp();

#pragma unroll
        for (int ks = 0; ks < 8; ks++) {
            const int kb8 = ks * 8;
            unsigned a[4];
            a[0] = __float_as_uint(smf[PS_OFF + m0 * LDP + kb8 + qc]);
            a[1] = __float_as_uint(smf[PS_OFF + (m0 + 8) * LDP + kb8 + qc]);
            a[2] = __float_as_uint(smf[PS_OFF + m0 * LDP + kb8 + qc + 4]);
            a[3] = __float_as_uint(smf[PS_OFF + (m0 + 8) * LDP + kb8 + qc + 4]);
#pragma unroll
            for (int nt = 0; nt < 16; nt++) {
                int n = nt * 8 + qr;
                uint2 bb = *(const uint2*)&Vb[n * LDVT + kb8 + 2 * qc];
                mma_tf32(o[nt], a, bb.x, bb.y);
            }
        }
    }

    // ================== epilogue: memory path ==================
    __syncthreads();

    const float* mptr = memp + (size_t)bh * HD_ * HD_;
#pragma unroll
    for (int it = 0; it < 16; it++) {
        int row = w + 8 * it;
        float4 v = *(const float4*)(mptr + (size_t)row * HD_ + lane * 4);
        *(uint4*)&smu[MS_OFF + row * LDM + lane * 4] =
            make_uint4(f2tf32(v.x), f2tf32(v.y), f2tf32(v.z), f2tf32(v.w));
    }
    if (tid < 128) smf[NS_OFF + tid] = normp[(size_t)bh * HD_ + tid];

#pragma unroll
    for (int ks = 0; ks < 16; ks++)
#pragma unroll
        for (int u = 0; u < 4; u++) {
            float qv = __uint_as_float(qa[ks][u]);
            float qf = qv > 0.f ? qv + 1.f : __expf(qv);
            qa[ks][u] = f2tf32(qf);
        }
    __syncthreads();

    float den0 = 0.f, den1 = 0.f;
#pragma unroll
    for (int ks = 0; ks < 16; ks++) {
        float n0 = smf[NS_OFF + 8 * ks + qc];
        float n4 = smf[NS_OFF + 8 * ks + qc + 4];
        den0 = fmaf(__uint_as_float(qa[ks][0]), n0, den0);
        den0 = fmaf(__uint_as_float(qa[ks][2]), n4, den0);
        den1 = fmaf(__uint_as_float(qa[ks][1]), n0, den1);
        den1 = fmaf(__uint_as_float(qa[ks][3]), n4, den1);
    }
    den0 += __shfl_xor_sync(0xffffffffu, den0, 1);
    den0 += __shfl_xor_sync(0xffffffffu, den0, 2);
    den1 += __shfl_xor_sync(0xffffffffu, den1, 1);
    den1 += __shfl_xor_sync(0xffffffffu, den1, 2);

    const float g  = 1.f / (1.f + __expf(-gatep[h]));
    const float og = 1.f - g;
    const float invl0 = og / lrow0, invl1 = og / lrow1;
    const float invd0 = g / den0,   invd1 = g / den1;

    const int l0 = qt * 128 + m0;
    float* dst0 = cb + ((size_t)b * L_ + l0) * (H_ * HD_) + h * HD_;
    float* dst1 = cb + ((size_t)b * L_ + l0 + 8) * (H_ * HD_) + h * HD_;

    const int p8 = (qc < 2) ? 4 * qc : 4 * (qc - 2) + 1;

#pragma unroll
    for (int pass = 0; pass < 2; pass++) {
        float ma[8][4];
#pragma unroll
        for (int nt = 0; nt < 8; nt++)
#pragma unroll
            for (int u = 0; u < 4; u++) ma[nt][u] = 0.f;

#pragma unroll
        for (int ks = 0; ks < 16; ks++) {
            const int kb8 = ks * 8;
#pragma unroll
            for (int nt = 0; nt < 8; nt++) {
                int n = (pass * 8 + nt) * 8 + qr;
                unsigned b0 = smu[MS_OFF + (kb8 + qc) * LDM + n];
                unsigned b1 = smu[MS_OFF + (kb8 + qc + 4) * LDM + n];
                mma_tf32(ma[nt], qa[ks], b0, b1);
            }
        }

#pragma unroll
        for (int nt = 0; nt < 8; nt++) {
            int gnt = pass * 8 + nt;
            int grp = gnt * 8;
            float r00 = rnd(ma[nt][0] * invd0 + o[gnt][0] * invl0);
            float r01 = rnd(ma[nt][1] * invd0 + o[gnt][1] * invl0);
            float r10 = rnd(ma[nt][2] * invd1 + o[gnt][2] * invl1);
            float r11 = rnd(ma[nt][3] * invd1 + o[gnt][3] * invl1);
            dst0[grp + p8]     = r00;
            dst0[grp + p8 + 2] = r01;
            dst1[grp + p8]     = r10;
            dst1[grp + p8 + 2] = r11;
        }
    }
}

// ---------------------------------------------------------------------------

extern "C" void kernel_launch(void* const* d_in, const int* in_sizes, int n_in,
                              void* d_out, int out_size)
{
    const float* x      = (const float*)d_in[0];
    const float* Wq     = (const float*)d_in[1];
    const float* Wk     = (const float*)d_in[2];
    const float* Wv     = (const float*)d_in[3];
    const float* Wo     = (const float*)d_in[4];
    const float* gate   = (const float*)d_in[5];
    const float* memory = (const float*)d_in[6];
    const float* norm   = (const float*)d_in[7];
    float* out = (float*)d_out;

    float *qb, *kb, *vb, *cb, *xt, *w0, *w1, *w2, *w3;
    cudaGetSymbolAddress((void**)&qb, g_q);
    cudaGetSymbolAddress((void**)&kb, g_k);
    cudaGetSymbolAddress((void**)&vb, g_v);
    cudaGetSymbolAddress((void**)&cb, g_c);
    cudaGetSymbolAddress((void**)&xt, g_xt);
    cudaGetSymbolAddress((void**)&w0, g_w0);
    cudaGetSymbolAddress((void**)&w1, g_w1);
    cudaGetSymbolAddress((void**)&w2, g_w2);
    cudaGetSymbolAddress((void**)&w3, g_w3);

    // launches 0-2: tf32 pre-rounding (split so gemm_qkv is the 4th launch =
    // ncu capture slot)
    cvt_x_kernel<<<2048, 256>>>((const float4*)x, (float4*)xt);
    cvt_w_kernel<<<2048, 256>>>((const float4*)Wq, (float4*)w0,
                                (const float4*)Wk, (float4*)w1);
    cvt_w_kernel<<<2048, 256>>>((const float4*)Wv, (float4*)w2,
                                (const float4*)Wo, (float4*)w3);

    cudaFuncSetAttribute(gemm_qkv, cudaFuncAttributeMaxDynamicSharedMemorySize, GEMM_SMEM);
    cudaFuncSetAttribute(gemm_out, cudaFuncAttributeMaxDynamicSharedMemorySize, GEMM_SMEM);

    // launch 3: merged Q/K/V projections (ncu capture slot)
    gemm_qkv<<<dim3(16, 32, 3), 256, GEMM_SMEM>>>(xt, w0, w1, w2, qb, kb, vb);

    // launch 4: rope
    int nrope = B_ * H_ * L_ * 64;
    rope_kernel<<<nrope / 256, 256>>>(qb, kb);

    // launch 5: attention
    cudaFuncSetAttribute(attn_tc, cudaFuncAttributeMaxDynamicSharedMemorySize, ATTN_SMEM);
    attn_tc<<<dim3(16, 32), 256, ATTN_SMEM>>>(qb, kb, vb, gate, memory, norm, cb);

    // launch 6: output projection
    gemm_out<<<dim3(16, 32), 256, GEMM_SMEM>>>(cb, w3, out, B_ * L_, H_ * HD_, D_);
}